// round 10
// baseline (speedup 1.0000x reference)
#include <cuda_runtime.h>
#include <cuda_bf16.h>

// XingLoss: P=16384 rows, N=1024 points (x,y) fp32. segn = N/4 = 256 segments/row.
// Segment i of row p uses points x[p, 3i .. 3i+3]:
//   c12 = cross(v1,v2) (sign only), c13 = cross(v1,v3)
//   term = (c12>=0 ? relu(-c13) : relu(c13)) * rsqrt(|v1|^2 * |v3|^2)
// out = scale * sum_all_terms / (P * segn)
//
// Each thread handles 2 adjacent segments. Needed floats [12t..12t+13] are
// loaded EXACTLY with 3x LDG.128 + 1x LDG.64 (56B useful = 56B loaded;
// 48t bytes -> 16B aligned, +48B -> 8B aligned). Streaming evict-first.
// Block = 256 thr = 2 rows x 128 thr, 8 iterations -> 16 rows/block,
// grid = 1024 -> one wave at 8 CTAs/SM. Last-block-done final reduction.

#define P_ROWS        16384
#define SEGN          256
#define NPTS          1024
#define ROWS_PER_BLK  16
#define GRID_BLKS     (P_ROWS / ROWS_PER_BLK)   // 1024

__device__ float g_partials[GRID_BLKS];
__device__ unsigned int g_counter;  // static-zero; last block resets each launch

// Decode a scalar of unknown dtype (int32 or fp32).
__device__ __forceinline__ float decode_scale(const int* sp) {
    if (sp == nullptr) return 1.0f;
    int bits = *sp;
    float f = __int_as_float(bits);
    float af = fabsf(f);
    if (af > 1e-30f && af < 1e30f) return f;
    return (float)bits;
}

// One segment: points q0..q3 as 8 consecutive floats f[0..7].
__device__ __forceinline__ float seg_term8(const float* f) {
    float v1x = f[2] - f[0], v1y = f[3] - f[1];
    float v2x = f[4] - f[2], v2y = f[5] - f[3];
    float v3x = f[6] - f[4], v3y = f[7] - f[5];

    float c12 = v1x * v2y - v1y * v2x;
    float c13 = v1x * v3y - v1y * v3x;
    float d1  = v1x * v1x + v1y * v1y;
    float d3  = v3x * v3x + v3y * v3y;

    float sel = (c12 >= 0.0f) ? fmaxf(-c13, 0.0f) : fmaxf(c13, 0.0f);
    return sel * rsqrtf(d1 * d3);
}

__global__ __launch_bounds__(256) void xing_fused_kernel(const float* __restrict__ x,
                                                         const int* __restrict__ scale_p,
                                                         float* __restrict__ out) {
    const int t    = threadIdx.x;
    const int lane = t & 31, wid = t >> 5;
    const int tl   = t & 127;          // thread within row (handles segs 2tl, 2tl+1)
    const int rsub = t >> 7;           // 0/1: which row of the pair
    const int row0 = blockIdx.x * ROWS_PER_BLK;

    // floats [12*tl ..] of each assigned row; byte offset 48*tl -> 16B aligned
    const float* basef = x + (size_t)(row0 + rsub) * (NPTS * 2) + 12 * tl;

    float acc = 0.0f;
    #pragma unroll 2
    for (int it = 0; it < ROWS_PER_BLK / 2; it++) {
        const float* rp = basef + (size_t)it * (2 * NPTS * 2);  // +2 rows per iter
        float4 r0 = __ldcs(reinterpret_cast<const float4*>(rp) + 0);
        float4 r1 = __ldcs(reinterpret_cast<const float4*>(rp) + 1);
        float4 r2 = __ldcs(reinterpret_cast<const float4*>(rp) + 2);
        float2 r3 = __ldcs(reinterpret_cast<const float2*>(rp + 12));  // 8B aligned

        float f[14];
        f[0]=r0.x;  f[1]=r0.y;  f[2]=r0.z;  f[3]=r0.w;
        f[4]=r1.x;  f[5]=r1.y;  f[6]=r1.z;  f[7]=r1.w;
        f[8]=r2.x;  f[9]=r2.y;  f[10]=r2.z; f[11]=r2.w;
        f[12]=r3.x; f[13]=r3.y;

        acc += seg_term8(f + 0);   // segment 2tl   : points 6tl..6tl+3
        acc += seg_term8(f + 6);   // segment 2tl+1 : points 6tl+3..6tl+6
    }

    // warp reduce
    #pragma unroll
    for (int off = 16; off > 0; off >>= 1)
        acc += __shfl_down_sync(0xFFFFFFFFu, acc, off);

    __shared__ float warp_sums[256 / 32];
    __shared__ int is_last;
    if (lane == 0) warp_sums[wid] = acc;
    __syncthreads();

    if (wid == 0) {
        float s = (lane < 256 / 32) ? warp_sums[lane] : 0.0f;
        #pragma unroll
        for (int off = 4; off > 0; off >>= 1)
            s += __shfl_down_sync(0xFFFFFFFFu, s, off);
        if (lane == 0) {
            g_partials[blockIdx.x] = s;
            __threadfence();  // once per block (1024 total) -> cheap
            unsigned int prev = atomicAdd(&g_counter, 1u);
            is_last = (prev == (unsigned int)(GRID_BLKS - 1)) ? 1 : 0;
        }
    }
    __syncthreads();

    if (is_last) {
        // 1024 partials / 256 threads = 4 loads each (L2 hits post-fence).
        float a = 0.0f;
        #pragma unroll
        for (int j = 0; j < GRID_BLKS / 256; j++)
            a += __ldcg(&g_partials[t + j * 256]);

        #pragma unroll
        for (int off = 16; off > 0; off >>= 1)
            a += __shfl_down_sync(0xFFFFFFFFu, a, off);

        if (lane == 0) warp_sums[wid] = a;
        __syncthreads();

        if (wid == 0) {
            float s = (lane < 256 / 32) ? warp_sums[lane] : 0.0f;
            #pragma unroll
            for (int off = 4; off > 0; off >>= 1)
                s += __shfl_down_sync(0xFFFFFFFFu, s, off);
            if (lane == 0) {
                float scale = decode_scale(scale_p);
                out[0] = s * (scale / ((float)SEGN * (float)P_ROWS));
                g_counter = 0;  // reset for next graph replay
            }
        }
    }
}

extern "C" void kernel_launch(void* const* d_in, const int* in_sizes, int n_in,
                              void* d_out, int out_size) {
    const float* x = (const float*)d_in[0];
    const int* scale_p = (n_in > 1) ? (const int*)d_in[1] : nullptr;
    float* out = (float*)d_out;

    xing_fused_kernel<<<GRID_BLKS, 256>>>(x, scale_p, out);
}

// round 13
// speedup vs baseline: 1.1356x; 1.1356x over previous
#include <cuda_runtime.h>
#include <cuda_bf16.h>

// XingLoss_31284541784235 — final kernel (R6-equivalent resubmission, round 12).
// Source hash intentionally perturbed vs R10/R11 (which hit back-to-back
// container failures) to dodge any artifact-cache poisoning; semantics and
// codegen-relevant structure are unchanged from the 15.1us measured optimum.
//
// Math: P=16384 rows, N=1024 points (x,y) fp32; segn=256 segments/row.
// Segment i of row p uses points x[p, 3i..3i+3]:
//   c12 = cross(v1,v2) (only its sign matters), c13 = cross(v1,v3)
//   term = (c12>=0 ? relu(-c13) : relu(c13)) * rsqrt(|v1|^2 |v3|^2)
//   out  = scale * sum(all terms) / (P * segn)
//
// Layout: thread handles segments (2tl, 2tl+1) via 4x uniform LDG.128 over
// floats [12tl..12tl+15] (48tl B -> 16B aligned; neighbor-thread 8B overlap is
// absorbed in shared L1tex wavefronts). Block = 2 rows x 128 thr, 8 iters ->
// 16 rows/block; grid=1024 -> one full wave (8 CTAs/SM, 31 regs), 56
// row-pairs/SM (minimal imbalance). Deterministic last-block-done reduction;
// g_counter reset each launch keeps graph replays clean.

#define P_ROWS        16384
#define SEGN          256
#define NPTS          1024
#define ROWS_PER_BLK  16
#define GRID_BLKS     (P_ROWS / ROWS_PER_BLK)   // 1024

__device__ float g_partials[GRID_BLKS];
__device__ unsigned int g_counter;  // static-zero; reset by last block each launch

// Decode a scalar of unknown dtype (int32 or fp32).
__device__ __forceinline__ float decode_scale(const int* sp) {
    if (sp == nullptr) return 1.0f;
    const int bits = *sp;
    const float f = __int_as_float(bits);
    const float af = fabsf(f);
    return (af > 1e-30f && af < 1e30f) ? f : (float)bits;
}

// One segment: points q0..q3 given as 8 consecutive floats f[0..7].
__device__ __forceinline__ float seg_term8(const float* f) {
    const float v1x = f[2] - f[0], v1y = f[3] - f[1];
    const float v3x = f[6] - f[4], v3y = f[7] - f[5];
    const float v2x = f[4] - f[2], v2y = f[5] - f[3];

    const float c12 = v1x * v2y - v1y * v2x;
    const float c13 = v1x * v3y - v1y * v3x;
    const float d1  = v1x * v1x + v1y * v1y;
    const float d3  = v3x * v3x + v3y * v3y;

    const float sel = (c12 >= 0.0f) ? fmaxf(-c13, 0.0f) : fmaxf(c13, 0.0f);
    return sel * rsqrtf(d1 * d3);
}

__global__ __launch_bounds__(256) void xing_fused_kernel(const float* __restrict__ x,
                                                         const int* __restrict__ scale_p,
                                                         float* __restrict__ out) {
    const int t    = threadIdx.x;
    const int lane = t & 31, wid = t >> 5;
    const int tl   = t & 127;          // thread-in-row: owns segments 2tl, 2tl+1
    const int rsub = t >> 7;           // 0/1: which row of the pair
    const int row0 = blockIdx.x * ROWS_PER_BLK;

    // floats [12*tl .. 12*tl+15] of each assigned row; 48*tl bytes -> 16B aligned
    const float4* base = reinterpret_cast<const float4*>(
        x + (size_t)(row0 + rsub) * (NPTS * 2) + 12 * tl);

    float acc = 0.0f;
    #pragma unroll 2
    for (int it = 0; it < ROWS_PER_BLK / 2; it++) {
        const float4* bp = base + (size_t)it * (2 * NPTS * 2 / 4);  // advance 2 rows
        const float4 r0 = bp[0];
        const float4 r1 = bp[1];
        const float4 r2 = bp[2];
        const float4 r3 = bp[3];

        float f[14];
        f[0]=r0.x;  f[1]=r0.y;  f[2]=r0.z;  f[3]=r0.w;
        f[4]=r1.x;  f[5]=r1.y;  f[6]=r1.z;  f[7]=r1.w;
        f[8]=r2.x;  f[9]=r2.y;  f[10]=r2.z; f[11]=r2.w;
        f[12]=r3.x; f[13]=r3.y;

        acc += seg_term8(f + 0);   // segment 2tl   : points 6tl..6tl+3
        acc += seg_term8(f + 6);   // segment 2tl+1 : points 6tl+3..6tl+6
    }

    // warp-level tree reduce
    #pragma unroll
    for (int off = 16; off > 0; off >>= 1)
        acc += __shfl_down_sync(0xFFFFFFFFu, acc, off);

    __shared__ float warp_sums[256 / 32];
    __shared__ int is_last;
    if (lane == 0) warp_sums[wid] = acc;
    __syncthreads();

    if (wid == 0) {
        float s = (lane < 256 / 32) ? warp_sums[lane] : 0.0f;
        #pragma unroll
        for (int off = 4; off > 0; off >>= 1)
            s += __shfl_down_sync(0xFFFFFFFFu, s, off);
        if (lane == 0) {
            g_partials[blockIdx.x] = s;
            __threadfence();  // once per block (1024 total): negligible
            const unsigned int prev = atomicAdd(&g_counter, 1u);
            is_last = (prev == (unsigned int)(GRID_BLKS - 1)) ? 1 : 0;
        }
    }
    __syncthreads();

    if (is_last) {
        // 1024 partials / 256 threads = 4 loads per thread (L2-resident).
        float a = 0.0f;
        #pragma unroll
        for (int j = 0; j < GRID_BLKS / 256; j++)
            a += __ldcg(&g_partials[t + j * 256]);

        #pragma unroll
        for (int off = 16; off > 0; off >>= 1)
            a += __shfl_down_sync(0xFFFFFFFFu, a, off);

        if (lane == 0) warp_sums[wid] = a;
        __syncthreads();

        if (wid == 0) {
            float s = (lane < 256 / 32) ? warp_sums[lane] : 0.0f;
            #pragma unroll
            for (int off = 4; off > 0; off >>= 1)
                s += __shfl_down_sync(0xFFFFFFFFu, s, off);
            if (lane == 0) {
                const float scale = decode_scale(scale_p);
                out[0] = s * (scale / ((float)SEGN * (float)P_ROWS));
                g_counter = 0;  // clean state for the next graph replay
            }
        }
    }
}

extern "C" void kernel_launch(void* const* d_in, const int* in_sizes, int n_in,
                              void* d_out, int out_size) {
    const float* x = (const float*)d_in[0];
    const int* scale_p = (n_in > 1) ? (const int*)d_in[1] : nullptr;
    float* out = (float*)d_out;

    xing_fused_kernel<<<GRID_BLKS, 256>>>(x, scale_p, out);
}

// round 14
// speedup vs baseline: 1.3400x; 1.1800x over previous
#include <cuda_runtime.h>
#include <cuda_bf16.h>

// XingLoss: P=16384 rows, N=1024 points (x,y) fp32. segn = N/4 = 256 segments/row.
// Segment i of row p uses points x[p, 3i..3i+3]:
//   c12 = cross(v1,v2) (sign only), c13 = cross(v1,v3)
//   term = (c12>=0 ? relu(-c13) : relu(c13)) * rsqrt(|v1|^2 |v3|^2)   in [0,1]
// out = scale * sum_all_terms / (P * segn)
//
// Streaming phase (unchanged, measured optimum): thread owns segments
// (2tl, 2tl+1) via 4x uniform LDG.128 over floats [12tl..12tl+15]; block =
// 2 rows x 128 thr, 8 iters -> 16 rows/block; grid=1024 -> one wave,
// 8 CTAs/SM @ ~31 regs.
//
// Completion protocol (NEW): one packed u64 atomicAdd per block.
//   mine = (1<<48) | round(block_partial * 2^24)     (partial in [0,4096])
//   fixed sum lives in bits [0,48): max ~7e13 < 2^48 (4096x headroom, no carry)
//   count lives in bits [48+): block seeing new count == 1024 is last; its
//   (old + mine) already holds the full sum -> writes out[0], resets g_acc.
// Integer adds are order-independent -> bit-deterministic across replays.
// Removes: 1024 __threadfence (CCTL.IVALL L1 flushes!), partials array,
// second reduction pass. Quantization error ~1e-11 relative.

#define P_ROWS        16384
#define SEGN          256
#define NPTS          1024
#define ROWS_PER_BLK  16
#define GRID_BLKS     (P_ROWS / ROWS_PER_BLK)   // 1024

#define FIX_BITS      24
#define COUNT_SHIFT   48

__device__ unsigned long long g_acc;  // static-zero; last block resets each launch

// Decode a scalar of unknown dtype (int32 or fp32).
__device__ __forceinline__ float decode_scale(const int* sp) {
    if (sp == nullptr) return 1.0f;
    const int bits = *sp;
    const float f = __int_as_float(bits);
    const float af = fabsf(f);
    return (af > 1e-30f && af < 1e30f) ? f : (float)bits;
}

// One segment: points q0..q3 given as 8 consecutive floats f[0..7].
__device__ __forceinline__ float seg_term8(const float* f) {
    const float v1x = f[2] - f[0], v1y = f[3] - f[1];
    const float v2x = f[4] - f[2], v2y = f[5] - f[3];
    const float v3x = f[6] - f[4], v3y = f[7] - f[5];

    const float c12 = v1x * v2y - v1y * v2x;
    const float c13 = v1x * v3y - v1y * v3x;
    const float d1  = v1x * v1x + v1y * v1y;
    const float d3  = v3x * v3x + v3y * v3y;

    const float sel = (c12 >= 0.0f) ? fmaxf(-c13, 0.0f) : fmaxf(c13, 0.0f);
    return sel * rsqrtf(d1 * d3);
}

__global__ __launch_bounds__(256) void xing_fused_kernel(const float* __restrict__ x,
                                                         const int* __restrict__ scale_p,
                                                         float* __restrict__ out) {
    const int t    = threadIdx.x;
    const int lane = t & 31, wid = t >> 5;
    const int tl   = t & 127;          // thread-in-row: owns segments 2tl, 2tl+1
    const int rsub = t >> 7;           // 0/1: which row of the pair
    const int row0 = blockIdx.x * ROWS_PER_BLK;

    // floats [12*tl .. 12*tl+15] of each assigned row; 48*tl bytes -> 16B aligned
    const float4* base = reinterpret_cast<const float4*>(
        x + (size_t)(row0 + rsub) * (NPTS * 2) + 12 * tl);

    float acc = 0.0f;
    #pragma unroll 2
    for (int it = 0; it < ROWS_PER_BLK / 2; it++) {
        const float4* bp = base + (size_t)it * (2 * NPTS * 2 / 4);  // advance 2 rows
        const float4 r0 = bp[0];
        const float4 r1 = bp[1];
        const float4 r2 = bp[2];
        const float4 r3 = bp[3];

        float f[14];
        f[0]=r0.x;  f[1]=r0.y;  f[2]=r0.z;  f[3]=r0.w;
        f[4]=r1.x;  f[5]=r1.y;  f[6]=r1.z;  f[7]=r1.w;
        f[8]=r2.x;  f[9]=r2.y;  f[10]=r2.z; f[11]=r2.w;
        f[12]=r3.x; f[13]=r3.y;

        acc += seg_term8(f + 0);   // segment 2tl   : points 6tl..6tl+3
        acc += seg_term8(f + 6);   // segment 2tl+1 : points 6tl+3..6tl+6
    }

    // warp-level tree reduce
    #pragma unroll
    for (int off = 16; off > 0; off >>= 1)
        acc += __shfl_down_sync(0xFFFFFFFFu, acc, off);

    __shared__ float warp_sums[256 / 32];
    if (lane == 0) warp_sums[wid] = acc;
    __syncthreads();

    if (wid == 0) {
        float s = (lane < 256 / 32) ? warp_sums[lane] : 0.0f;
        #pragma unroll
        for (int off = 4; off > 0; off >>= 1)
            s += __shfl_down_sync(0xFFFFFFFFu, s, off);
        if (lane == 0) {
            // s in [0, 4096]; fixed-point in double is exact to well below 2^-24
            const unsigned long long fixed =
                (unsigned long long)((double)s * (double)(1u << FIX_BITS) + 0.5);
            const unsigned long long mine = (1ULL << COUNT_SHIFT) | fixed;
            const unsigned long long old  = atomicAdd(&g_acc, mine);
            const unsigned long long tot  = old + mine;
            if ((tot >> COUNT_SHIFT) == (unsigned long long)GRID_BLKS) {
                // I'm the last block; tot already holds the complete sum.
                const double sum =
                    (double)(tot & ((1ULL << COUNT_SHIFT) - 1)) /
                    (double)(1u << FIX_BITS);
                const float scale = decode_scale(scale_p);
                out[0] = (float)(sum * (double)scale /
                                 ((double)SEGN * (double)P_ROWS));
                g_acc = 0;  // clean state for the next graph replay
            }
        }
    }
}

extern "C" void kernel_launch(void* const* d_in, const int* in_sizes, int n_in,
                              void* d_out, int out_size) {
    const float* x = (const float*)d_in[0];
    const int* scale_p = (n_in > 1) ? (const int*)d_in[1] : nullptr;
    float* out = (float*)d_out;

    xing_fused_kernel<<<GRID_BLKS, 256>>>(x, scale_p, out);
}